// round 3
// baseline (speedup 1.0000x reference)
#include <cuda_runtime.h>

// out[b,s,:] = x[b,s,:] + (positions[b,s] >= 0 ? pe[positions[b,s], :] : 0)
// x: [256,365,512] f32, positions: [256,365] i32, pe: [365,512] f32
// D = 512 floats = 128 float4 per row. Each thread handles 2 consecutive
// float4s (64 threads per row) for MLP=2 per thread and halved index math.

static constexpr int D4 = 128;  // 512 / 4

__global__ void posenc_kernel(const float4* __restrict__ x,
                              const int*    __restrict__ pos,
                              const float4* __restrict__ pe,
                              float4*       __restrict__ out,
                              int n8) {
    int t = blockIdx.x * blockDim.x + threadIdx.x;
    if (t >= n8) return;
    int i = t * 2;                 // first float4 index
    int row = i >> 7;              // / D4  (both chunks in same row: 2 | 128)
    int col = i & (D4 - 1);        // % D4
    int p = pos[row];              // warp-uniform (64 threads/row, 32-aligned)

    float4 v0 = x[i];
    float4 v1 = x[i + 1];
    if (p >= 0) {
        const float4* per = pe + p * D4 + col;
        float4 e0 = per[0];
        float4 e1 = per[1];
        v0.x += e0.x; v0.y += e0.y; v0.z += e0.z; v0.w += e0.w;
        v1.x += e1.x; v1.y += e1.y; v1.z += e1.z; v1.w += e1.w;
    }
    out[i]     = v0;
    out[i + 1] = v1;
}

extern "C" void kernel_launch(void* const* d_in, const int* in_sizes, int n_in,
                              void* d_out, int out_size) {
    const float4* x   = (const float4*)d_in[0];
    const int*    pos = (const int*)d_in[1];
    const float4* pe  = (const float4*)d_in[2];
    float4*       out = (float4*)d_out;

    // in_sizes[0] = 256*365*512, divisible by 8; n8 threads, 2 float4 each.
    int n8 = in_sizes[0] / 8;
    int threads = 256;
    int blocks = (n8 + threads - 1) / threads;
    posenc_kernel<<<blocks, threads>>>(x, pos, pe, out, n8);
}

// round 10
// speedup vs baseline: 1.0091x; 1.0091x over previous
#include <cuda_runtime.h>

// out[b,s,:] = x[b,s,:] + (positions[b,s] >= 0 ? pe[positions[b,s], :] : 0)
// x: [256,365,512] f32, positions: [256,365] i32, pe: [365,512] f32
//
// One warp per row (D = 512 f32 = 128 float4). Lane l handles float4
// columns l, l+32, l+64, l+96 -> every LDG/STG.128 is a fully coalesced
// 512B contiguous access. 4 x-loads (+4 pe-loads) front-batched per thread
// for high MLP. x/out touched once -> streaming (.cs) hints; pe (747 KB)
// stays L2-resident for the gather.

static constexpr int D4   = 128;              // float4s per row
static constexpr int ROWS = 256 * 365;        // 93440 rows (one warp each)

__global__ void __launch_bounds__(256) posenc_kernel(
        const float4* __restrict__ x,
        const int*    __restrict__ pos,
        const float4* __restrict__ pe,
        float4*       __restrict__ out) {
    int warp = (blockIdx.x * blockDim.x + threadIdx.x) >> 5;  // == row
    int lane = threadIdx.x & 31;

    long base = (long)warp * D4 + lane;
    const float4* xr = x + base;
    int p = pos[warp];                         // warp-uniform broadcast

    // Front-batched streaming loads (evict-first: x is read exactly once)
    float4 v0 = __ldcs(xr);
    float4 v1 = __ldcs(xr + 32);
    float4 v2 = __ldcs(xr + 64);
    float4 v3 = __ldcs(xr + 96);

    if (p >= 0) {
        const float4* per = pe + p * D4 + lane;   // L2-resident table
        float4 e0 = __ldg(per);
        float4 e1 = __ldg(per + 32);
        float4 e2 = __ldg(per + 64);
        float4 e3 = __ldg(per + 96);
        v0.x += e0.x; v0.y += e0.y; v0.z += e0.z; v0.w += e0.w;
        v1.x += e1.x; v1.y += e1.y; v1.z += e1.z; v1.w += e1.w;
        v2.x += e2.x; v2.y += e2.y; v2.z += e2.z; v2.w += e2.w;
        v3.x += e3.x; v3.y += e3.y; v3.z += e3.z; v3.w += e3.w;
    }

    float4* outr = out + base;
    __stcs(outr,      v0);                    // streaming store (write-once)
    __stcs(outr + 32, v1);
    __stcs(outr + 64, v2);
    __stcs(outr + 96, v3);
}

extern "C" void kernel_launch(void* const* d_in, const int* in_sizes, int n_in,
                              void* d_out, int out_size) {
    const float4* x   = (const float4*)d_in[0];
    const int*    pos = (const int*)d_in[1];
    const float4* pe  = (const float4*)d_in[2];
    float4*       out = (float4*)d_out;

    // ROWS warps total, 8 warps (256 threads) per block -> exact cover.
    int blocks = ROWS / 8;                    // 93440 / 8 = 11680
    posenc_kernel<<<blocks, 256>>>(x, pos, pe, out);
}